// round 15
// baseline (speedup 1.0000x reference)
#include <cuda_runtime.h>
#include <math.h>

#define D_MODEL 1024
#define N_EXP   32
#define D_LOW   64
#define N_TOK   1024
#define N_PAIR  (N_TOK * 2)
#define OUT_ELEMS (N_TOK * D_MODEL)
#define KSPLIT  8                    // k3 k-split (each block: 2 chunks of 64 k)
#define LSPLIT  8                    // k2a logit k-split
#define PS      (N_PAIR * D_LOW)     // 131072 partials per k-slice

// ---------------- scratch ------------------------------------------------------
__device__ float g_wr[N_EXP * D_MODEL];
__device__ int   g_cnt[N_EXP];
__device__ float g_sumprob[N_EXP];
__device__ int   g_btok[N_EXP * N_TOK];
__device__ float g_bwgt[N_EXP * N_TOK];
__device__ int   g_pslot[N_TOK * 2];
__device__ float g_lgp[LSPLIT * N_TOK * N_EXP];  // k-split logit partials
__device__ float g_actp[KSPLIT * PS];            // k-split down partials (4MB)
__device__ float g_acts[PS];                     // tf32(gelu(feats)), pair-compact
__device__ float g_y[N_PAIR * D_MODEL];          // weighted per-pair up output

// ---------------- helpers ------------------------------------------------------
__device__ __forceinline__ unsigned f2tf(float f) {
    unsigned r;
    asm("cvt.rna.tf32.f32 %0, %1;" : "=r"(r) : "f"(f));
    return r;
}
__device__ __forceinline__ uint4 f2tf4(float4 v) {
    return make_uint4(f2tf(v.x), f2tf(v.y), f2tf(v.z), f2tf(v.w));
}
// D += A(16x8,row) * B(8x8,col): tf32 inputs, f32 accumulate
#define MMA_TF32(d, a, b0, b1)                                                  \
    asm("mma.sync.aligned.m16n8k8.row.col.f32.tf32.tf32.f32 "                   \
        "{%0,%1,%2,%3},{%4,%5,%6,%7},{%8,%9},{%0,%1,%2,%3};"                    \
        : "+f"((d)[0]), "+f"((d)[1]), "+f"((d)[2]), "+f"((d)[3])                \
        : "r"((a)[0]), "r"((a)[1]), "r"((a)[2]), "r"((a)[3]), "r"(b0), "r"(b1))

__device__ __forceinline__ float dot4(float4 a, float4 b) {
    return a.x * b.x + a.y * b.y + a.z * b.z + a.w * b.w;
}
__device__ __forceinline__ float gelu_exact(float v) {
    return 0.5f * v * (1.0f + erff(v * 0.70710678118654752440f));
}
// exclusive prefix of g_cnt at expert e (all 32 lanes participate)
__device__ __forceinline__ int expert_off(int lane, int e) {
    int cc = g_cnt[lane];
    int sc = cc;
#pragma unroll
    for (int o = 1; o < 32; o <<= 1) {
        int v = __shfl_up_sync(0xffffffffu, sc, o);
        if (lane >= o) sc += v;
    }
    return __shfl_sync(0xffffffffu, sc - cc, e);
}

// ---------------- K1: fold router_w into w_down -> g_wr; zero accumulators ----
__global__ void k1_fold(const float* __restrict__ w_down,
                        const float* __restrict__ router_w) {
    __shared__ float rs[D_LOW];
    int tid = threadIdx.x;
    if (blockIdx.x == 0 && tid < N_EXP) { g_cnt[tid] = 0; g_sumprob[tid] = 0.f; }
    if (tid < D_LOW) rs[tid] = router_w[tid];
    __syncthreads();
    int idx = blockIdx.x * 256 + tid;
    int e = idx >> 10;
    int d = idx & (D_MODEL - 1);
    const float* wb = w_down + (e << 6) * D_MODEL + d;
    float acc = 0.f;
#pragma unroll 8
    for (int l = 0; l < D_LOW; l++)
        acc = fmaf(wb[l * D_MODEL], rs[l], acc);
    g_wr[idx] = acc;
}

// ---------------- K2a: logits GEMM (exact fp32), k-split by 8 ------------------
__global__ __launch_bounds__(256) void k2a_logits(const float* __restrict__ x) {
    __shared__ float4 xs4[32 * 33];
    __shared__ float4 wr4[32 * 33];
    const int tid = threadIdx.x;
    const int tt = blockIdx.x, kc = blockIdx.y;
    const int t = tid & 31, eg = tid >> 5;
    const float4* x4 = (const float4*)x;
    const float4* w4 = (const float4*)g_wr;

    const int k0q = kc * 32;
#pragma unroll
    for (int i = 0; i < 4; i++) {
        int j = tid + i * 256;
        int r = j >> 5, c = j & 31;
        xs4[r * 33 + c] = x4[(tt * 32 + r) * (D_MODEL / 4) + k0q + c];
        wr4[r * 33 + c] = w4[r * (D_MODEL / 4) + k0q + c];
    }
    __syncthreads();
    float acc0 = 0.f, acc1 = 0.f, acc2 = 0.f, acc3 = 0.f;
#pragma unroll 8
    for (int k4 = 0; k4 < 32; k4++) {
        float4 xv = xs4[t * 33 + k4];
        acc0 += dot4(xv, wr4[(eg * 4 + 0) * 33 + k4]);
        acc1 += dot4(xv, wr4[(eg * 4 + 1) * 33 + k4]);
        acc2 += dot4(xv, wr4[(eg * 4 + 2) * 33 + k4]);
        acc3 += dot4(xv, wr4[(eg * 4 + 3) * 33 + k4]);
    }
    const int n = tt * 32 + t;
    ((float4*)g_lgp)[kc * (N_TOK * N_EXP / 4) + n * 8 + eg] =
        make_float4(acc0, acc1, acc2, acc3);
}

// ---------------- K2c: reduce partials + softmax + top-2 + bucketize ----------
__global__ void k2c_route() {
    const int tid = threadIdx.x;
    const int lane = tid & 31, warp = tid >> 5;
    const int n = blockIdx.x * 8 + warp;

    float v = 0.f;
#pragma unroll
    for (int p = 0; p < LSPLIT; p++)
        v += g_lgp[p * (N_TOK * N_EXP) + n * N_EXP + lane];

    float m = v;
#pragma unroll
    for (int o = 16; o; o >>= 1) m = fmaxf(m, __shfl_xor_sync(0xffffffffu, m, o));
    float ex = expf(v - m);
    float s = ex;
#pragma unroll
    for (int o = 16; o; o >>= 1) s += __shfl_xor_sync(0xffffffffu, s, o);
    float prob = ex / s;
    atomicAdd(&g_sumprob[lane], prob);

    float bv = v; int bi = lane;
#pragma unroll
    for (int o = 16; o; o >>= 1) {
        float ov = __shfl_xor_sync(0xffffffffu, bv, o);
        int   oi = __shfl_xor_sync(0xffffffffu, bi, o);
        if (ov > bv || (ov == bv && oi < bi)) { bv = ov; bi = oi; }
    }
    int i0 = bi;
    float v2 = (lane == i0) ? -INFINITY : v;
    float bv2 = v2; int bi2 = lane;
#pragma unroll
    for (int o = 16; o; o >>= 1) {
        float ov = __shfl_xor_sync(0xffffffffu, bv2, o);
        int   oi = __shfl_xor_sync(0xffffffffu, bi2, o);
        if (ov > bv2 || (ov == bv2 && oi < bi2)) { bv2 = ov; bi2 = oi; }
    }
    int i1 = bi2;
    float p0 = __shfl_sync(0xffffffffu, prob, i0);
    float p1 = __shfl_sync(0xffffffffu, prob, i1);
    if (lane == 0) {
        float inv = 1.f / (p0 + p1);
        int s0 = atomicAdd(&g_cnt[i0], 1);
        g_btok[i0 * N_TOK + s0] = n;
        g_bwgt[i0 * N_TOK + s0] = p0 * inv;
        g_pslot[n * 2 + 0] = i0 * N_TOK + s0;
        int s1 = atomicAdd(&g_cnt[i1], 1);
        g_btok[i1 * N_TOK + s1] = n;
        g_bwgt[i1 * N_TOK + s1] = p1 * inv;
        g_pslot[n * 2 + 1] = i1 * N_TOK + s1;
    }
}

// ---------------- K3: down-proj partials via tf32 mma, cvt-at-fill -------------
// grid (8 k-groups, 32 experts, 2 token-tiles), 256 threads.
// Block: 64 tok x 64 l x 128 k (2 chunks of 64 k, register-accumulated).
__global__ __launch_bounds__(256, 4)
void k3_down(const float* __restrict__ x, const float* __restrict__ w_down) {
    __shared__ unsigned ws[D_LOW * 68];   // [64 l][64 k + pad], tf32 bits
    __shared__ unsigned xs[64 * 68];      // [64 tok][64 k + pad], tf32 bits

    const int e = blockIdx.y;
    const int kg = blockIdx.x;            // 0..7 -> k range [kg*128, +128)
    const int cnt = g_cnt[e];
    const int tile0 = blockIdx.z * 64;
    if (tile0 >= cnt) return;
    const int tid = threadIdx.x;
    const int off = expert_off(tid & 31, e);

    const float4* wd4 = (const float4*)w_down;
    const float4* x4g = (const float4*)x;
    const int lane = tid & 31, warp = tid >> 5;
    const int mb = (warp & 3) * 16;       // token block
    const int nb = (warp >> 2) * 32;      // l block
    const int grp = lane >> 2, tig = lane & 3;
    const int r0 = tid >> 4, cq0 = tid & 15;

    for (int t0 = tile0; t0 < cnt; t0 += 128) {
        float acc[4][4];
#pragma unroll
        for (int nt = 0; nt < 4; nt++)
#pragma unroll
            for (int c = 0; c < 4; c++) acc[nt][c] = 0.f;

#pragma unroll
        for (int kk = 0; kk < 2; kk++) {
            const int kq = (kg * 2 + kk) * 16;        // f4 offset in k
            __syncthreads();                          // prev readers done
#pragma unroll
            for (int i = 0; i < 4; i++) {             // ws: 1024 f4
                int j = tid + i * 256;
                int l = j >> 4, cq = j & 15;
                *(uint4*)(ws + l * 68 + cq * 4) =
                    f2tf4(wd4[(e * D_LOW + l) * (D_MODEL / 4) + kq + cq]);
            }
#pragma unroll
            for (int j = 0; j < 4; j++) {             // xs: 64 rows x 16 f4
                int idx = t0 + r0 + 16 * j; if (idx >= cnt) idx = cnt - 1;
                *(uint4*)(xs + (r0 + 16 * j) * 68 + cq0 * 4) =
                    f2tf4(x4g[g_btok[e * N_TOK + idx] * (D_MODEL / 4) + kq + cq0]);
            }
            __syncthreads();

#pragma unroll
            for (int k0 = 0; k0 < 64; k0 += 8) {
                unsigned a[4];
                a[0] = xs[(mb + grp    ) * 68 + k0 + tig    ];
                a[1] = xs[(mb + grp + 8) * 68 + k0 + tig    ];
                a[2] = xs[(mb + grp    ) * 68 + k0 + tig + 4];
                a[3] = xs[(mb + grp + 8) * 68 + k0 + tig + 4];
#pragma unroll
                for (int nt = 0; nt < 4; nt++) {
                    unsigned b0 = ws[(nb + nt * 8 + grp) * 68 + k0 + tig    ];
                    unsigned b1 = ws[(nb + nt * 8 + grp) * 68 + k0 + tig + 4];
                    MMA_TF32(acc[nt], a, b0, b1);
                }
            }
        }

        // store D fragments: row = mb+grp(+8), col = nb + nt*8 + 2*tig(+1)
#pragma unroll
        for (int nt = 0; nt < 4; nt++) {
#pragma unroll
            for (int h = 0; h < 2; h++) {
                int s = t0 + mb + grp + 8 * h;
                if (s < cnt) {
                    int col = nb + nt * 8 + 2 * tig;
                    *(float2*)&g_actp[((kg * N_PAIR + off + s) << 6) + col] =
                        make_float2(acc[nt][2 * h], acc[nt][2 * h + 1]);
                }
            }
        }
    }
}

// ---------------- K3g: sum 8 k-slices + GELU -> tf32 (+ aux loss) --------------
__global__ void k3g_gelu(float* out, int write_aux) {
    int tid = threadIdx.x;
    if (blockIdx.x == 0 && tid < 32 && write_aux) {
        float v = g_sumprob[tid] * (float)g_cnt[tid];
#pragma unroll
        for (int o = 16; o; o >>= 1) v += __shfl_xor_sync(0xffffffffu, v, o);
        if (tid == 0)
            out[OUT_ELEMS] = (float)N_EXP * v / ((float)N_TOK * (float)N_TOK);
    }
    int i = blockIdx.x * 256 + tid;               // 128*256 = PS/4
    const float4* ap4 = (const float4*)g_actp;
    float4 s = ap4[i];
#pragma unroll
    for (int k = 1; k < KSPLIT; k++) {
        float4 v = ap4[k * (PS / 4) + i];
        s.x += v.x; s.y += v.y; s.z += v.z; s.w += v.w;
    }
    // store tf32 bit patterns of gelu(s) — k4 consumes these directly
    uint4 o4 = make_uint4(f2tf(gelu_exact(s.x)), f2tf(gelu_exact(s.y)),
                          f2tf(gelu_exact(s.z)), f2tf(gelu_exact(s.w)));
    ((uint4*)g_acts)[i] = o4;
}

// ---------------- K4: up-proj via tf32 mma, cvt-at-fill ------------------------
// grid (16 d-tiles, 32 experts, 2 token-tiles), 256 threads.
// Block: 64 tok x 64 d x 64 l. Warp w: tokens [(w&3)*16), d [(w>>2)*32).
__global__ __launch_bounds__(256, 4)
void k4_up(const float* __restrict__ w_up) {
    __shared__ unsigned wu_s[64 * 68];    // [64 d][64 l + pad], tf32 (transposed)
    __shared__ unsigned as_s[64 * 68];    // [64 tok][64 l + pad], tf32 bits

    const int e = blockIdx.y;
    const int dt = blockIdx.x;
    const int cnt = g_cnt[e];
    const int tile0 = blockIdx.z * 64;
    if (tile0 >= cnt) return;
    const int tid = threadIdx.x;
    const int off = expert_off(tid & 31, e);

    // transpose w_up[e][l][dt*64 + d] -> wu_s[d][l], converting to tf32
#pragma unroll
    for (int i = 0; i < 4; i++) {
        int j = tid + i * 256;
        int d = j & 63, lg = j >> 6;
        const float* base = w_up + (e * D_LOW + lg * 4) * D_MODEL + dt * 64 + d;
        *(uint4*)(wu_s + d * 68 + lg * 4) =
            make_uint4(f2tf(base[0]), f2tf(base[D_MODEL]),
                       f2tf(base[2 * D_MODEL]), f2tf(base[3 * D_MODEL]));
    }

    const int lane = tid & 31, warp = tid >> 5;
    const int mb = (warp & 3) * 16;       // token block
    const int nb = (warp >> 2) * 32;      // d block
    const int grp = lane >> 2, tig = lane & 3;
    const int r0 = tid >> 4, cq0 = tid & 15;
    const uint4* a4g = (const uint4*)g_acts;      // already tf32 bits

    for (int t0 = tile0; t0 < cnt; t0 += 128) {
#pragma unroll
        for (int j = 0; j < 4; j++) {
            int idx = t0 + r0 + 16 * j; if (idx >= cnt) idx = cnt - 1;
            *(uint4*)(as_s + (r0 + 16 * j) * 68 + cq0 * 4) =
                a4g[(off + idx) * (D_LOW / 4) + cq0];
        }
        __syncthreads();

        float acc[4][4];
#pragma unroll
        for (int nt = 0; nt < 4; nt++)
#pragma unroll
            for (int c = 0; c < 4; c++) acc[nt][c] = 0.f;

#pragma unroll
        for (int k0 = 0; k0 < 64; k0 += 8) {
            unsigned a[4];
            a[0] = as_s[(mb + grp    ) * 68 + k0 + tig    ];
            a[1] = as_s[(mb + grp + 8) * 68 + k0 + tig    ];
            a[2] = as_s[(mb + grp    ) * 68 + k0 + tig + 4];
            a[3] = as_s[(mb + grp + 8) * 68 + k0 + tig + 4];
#pragma unroll
            for (int nt = 0; nt < 4; nt++) {
                unsigned b0 = wu_s[(nb + nt * 8 + grp) * 68 + k0 + tig    ];
                unsigned b1 = wu_s[(nb + nt * 8 + grp) * 68 + k0 + tig + 4];
                MMA_TF32(acc[nt], a, b0, b1);
            }
        }

        // store: row token s = t0+mb+grp(+8), col d = dt*64 + nb + nt*8 + 2*tig
#pragma unroll
        for (int h = 0; h < 2; h++) {
            int s = t0 + mb + grp + 8 * h;
            if (s < cnt) {
                float w = g_bwgt[e * N_TOK + s];
                float* yrow = g_y + (off + s) * D_MODEL + dt * 64;
#pragma unroll
                for (int nt = 0; nt < 4; nt++) {
                    int col = nb + nt * 8 + 2 * tig;
                    *(float2*)&yrow[col] =
                        make_float2(w * acc[nt][2 * h], w * acc[nt][2 * h + 1]);
                }
            }
        }
        __syncthreads();
    }
}

// ---------------- K5: gather-combine the two pairs per token ------------------
__global__ void k5_combine(float* __restrict__ out) {
    const int n = blockIdx.x;
    const int tid = threadIdx.x;
    const int lane = tid & 31;
    int cc = g_cnt[lane];
    int sc = cc;
#pragma unroll
    for (int o = 1; o < 32; o <<= 1) {
        int v = __shfl_up_sync(0xffffffffu, sc, o);
        if (lane >= o) sc += v;
    }
    int offl = sc - cc;
    int v0 = g_pslot[n * 2 + 0];
    int v1 = g_pslot[n * 2 + 1];
    int p0 = __shfl_sync(0xffffffffu, offl, v0 >> 10) + (v0 & (N_TOK - 1));
    int p1 = __shfl_sync(0xffffffffu, offl, v1 >> 10) + (v1 & (N_TOK - 1));
    const float4* y4 = (const float4*)g_y;
    float4 a = y4[p0 * (D_MODEL / 4) + tid];
    float4 b = y4[p1 * (D_MODEL / 4) + tid];
    ((float4*)out)[n * (D_MODEL / 4) + tid] =
        make_float4(a.x + b.x, a.y + b.y, a.z + b.z, a.w + b.w);
}

// ---------------- launch ------------------------------------------------------
extern "C" void kernel_launch(void* const* d_in, const int* in_sizes, int n_in,
                              void* d_out, int out_size) {
    const float* x        = (const float*)d_in[0];
    const float* w_down   = (const float*)d_in[1];
    const float* router_w = (const float*)d_in[2];
    const float* w_up     = (const float*)d_in[3];
    float* out = (float*)d_out;

    k1_fold<<<128, 256>>>(w_down, router_w);
    k2a_logits<<<dim3(32, LSPLIT), 256>>>(x);
    k2c_route<<<128, 256>>>();
    k3_down<<<dim3(KSPLIT, N_EXP, 2), 256>>>(x, w_down);
    k3g_gelu<<<128, 256>>>(out, out_size > OUT_ELEMS ? 1 : 0);
    k4_up<<<dim3(16, N_EXP, 2), 256>>>(w_up);
    k5_combine<<<N_TOK, 256>>>(out);
}

// round 16
// speedup vs baseline: 1.0526x; 1.0526x over previous
#include <cuda_runtime.h>
#include <math.h>

#define D_MODEL 1024
#define N_EXP   32
#define D_LOW   64
#define N_TOK   1024
#define N_PAIR  (N_TOK * 2)
#define OUT_ELEMS (N_TOK * D_MODEL)
#define KSPLIT  16
#define LSPLIT  8                    // k2a logit k-split
#define PS      (N_PAIR * D_LOW)     // 131072 partials per k-slice

// ---------------- scratch ------------------------------------------------------
__device__ float g_wr[N_EXP * D_MODEL];
__device__ int   g_cnt[N_EXP];
__device__ float g_sumprob[N_EXP];
__device__ int   g_btok[N_EXP * N_TOK];
__device__ float g_bwgt[N_EXP * N_TOK];
__device__ int   g_pslot[N_TOK * 2];
__device__ float g_lgp[LSPLIT * N_TOK * N_EXP];  // k-split logit partials
__device__ float g_actp[KSPLIT * PS];            // k-split down partials (8MB)
__device__ float g_acts[PS];                     // tf32(gelu(feats)), pair-compact
__device__ float g_y[N_PAIR * D_MODEL];          // weighted per-pair up output

// ---------------- helpers ------------------------------------------------------
__device__ __forceinline__ unsigned f2tf(float f) {
    unsigned r;
    asm("cvt.rna.tf32.f32 %0, %1;" : "=r"(r) : "f"(f));
    return r;
}
__device__ __forceinline__ uint4 f2tf4(float4 v) {
    return make_uint4(f2tf(v.x), f2tf(v.y), f2tf(v.z), f2tf(v.w));
}
// D += A(16x8,row) * B(8x8,col): tf32 inputs, f32 accumulate
#define MMA_TF32(d, a, b0, b1)                                                  \
    asm("mma.sync.aligned.m16n8k8.row.col.f32.tf32.tf32.f32 "                   \
        "{%0,%1,%2,%3},{%4,%5,%6,%7},{%8,%9},{%0,%1,%2,%3};"                    \
        : "+f"((d)[0]), "+f"((d)[1]), "+f"((d)[2]), "+f"((d)[3])                \
        : "r"((a)[0]), "r"((a)[1]), "r"((a)[2]), "r"((a)[3]), "r"(b0), "r"(b1))

__device__ __forceinline__ float dot4(float4 a, float4 b) {
    return a.x * b.x + a.y * b.y + a.z * b.z + a.w * b.w;
}
__device__ __forceinline__ float gelu_exact(float v) {
    return 0.5f * v * (1.0f + erff(v * 0.70710678118654752440f));
}
// exclusive prefix of g_cnt at expert e (all 32 lanes participate)
__device__ __forceinline__ int expert_off(int lane, int e) {
    int cc = g_cnt[lane];
    int sc = cc;
#pragma unroll
    for (int o = 1; o < 32; o <<= 1) {
        int v = __shfl_up_sync(0xffffffffu, sc, o);
        if (lane >= o) sc += v;
    }
    return __shfl_sync(0xffffffffu, sc - cc, e);
}

// ---------------- K1: fold router_w into w_down -> g_wr; zero accumulators ----
__global__ void k1_fold(const float* __restrict__ w_down,
                        const float* __restrict__ router_w) {
    __shared__ float rs[D_LOW];
    int tid = threadIdx.x;
    if (blockIdx.x == 0 && tid < N_EXP) { g_cnt[tid] = 0; g_sumprob[tid] = 0.f; }
    if (tid < D_LOW) rs[tid] = router_w[tid];
    __syncthreads();
    int idx = blockIdx.x * 256 + tid;
    int e = idx >> 10;
    int d = idx & (D_MODEL - 1);
    const float* wb = w_down + (e << 6) * D_MODEL + d;
    float acc = 0.f;
#pragma unroll 8
    for (int l = 0; l < D_LOW; l++)
        acc = fmaf(wb[l * D_MODEL], rs[l], acc);
    g_wr[idx] = acc;
}

// ---------------- K2a: logits GEMM (exact fp32), k-split by 8 ------------------
__global__ __launch_bounds__(256) void k2a_logits(const float* __restrict__ x) {
    __shared__ float4 xs4[32 * 33];
    __shared__ float4 wr4[32 * 33];
    const int tid = threadIdx.x;
    const int tt = blockIdx.x, kc = blockIdx.y;
    const int t = tid & 31, eg = tid >> 5;
    const float4* x4 = (const float4*)x;
    const float4* w4 = (const float4*)g_wr;

    const int k0q = kc * 32;
#pragma unroll
    for (int i = 0; i < 4; i++) {
        int j = tid + i * 256;
        int r = j >> 5, c = j & 31;
        xs4[r * 33 + c] = x4[(tt * 32 + r) * (D_MODEL / 4) + k0q + c];
        wr4[r * 33 + c] = w4[r * (D_MODEL / 4) + k0q + c];
    }
    __syncthreads();
    float acc0 = 0.f, acc1 = 0.f, acc2 = 0.f, acc3 = 0.f;
#pragma unroll 8
    for (int k4 = 0; k4 < 32; k4++) {
        float4 xv = xs4[t * 33 + k4];
        acc0 += dot4(xv, wr4[(eg * 4 + 0) * 33 + k4]);
        acc1 += dot4(xv, wr4[(eg * 4 + 1) * 33 + k4]);
        acc2 += dot4(xv, wr4[(eg * 4 + 2) * 33 + k4]);
        acc3 += dot4(xv, wr4[(eg * 4 + 3) * 33 + k4]);
    }
    const int n = tt * 32 + t;
    ((float4*)g_lgp)[kc * (N_TOK * N_EXP / 4) + n * 8 + eg] =
        make_float4(acc0, acc1, acc2, acc3);
}

// ---------------- K2c: reduce partials + softmax + top-2 + bucketize ----------
__global__ void k2c_route() {
    const int tid = threadIdx.x;
    const int lane = tid & 31, warp = tid >> 5;
    const int n = blockIdx.x * 8 + warp;

    float v = 0.f;
#pragma unroll
    for (int p = 0; p < LSPLIT; p++)
        v += g_lgp[p * (N_TOK * N_EXP) + n * N_EXP + lane];

    float m = v;
#pragma unroll
    for (int o = 16; o; o >>= 1) m = fmaxf(m, __shfl_xor_sync(0xffffffffu, m, o));
    float ex = expf(v - m);
    float s = ex;
#pragma unroll
    for (int o = 16; o; o >>= 1) s += __shfl_xor_sync(0xffffffffu, s, o);
    float prob = ex / s;
    atomicAdd(&g_sumprob[lane], prob);

    float bv = v; int bi = lane;
#pragma unroll
    for (int o = 16; o; o >>= 1) {
        float ov = __shfl_xor_sync(0xffffffffu, bv, o);
        int   oi = __shfl_xor_sync(0xffffffffu, bi, o);
        if (ov > bv || (ov == bv && oi < bi)) { bv = ov; bi = oi; }
    }
    int i0 = bi;
    float v2 = (lane == i0) ? -INFINITY : v;
    float bv2 = v2; int bi2 = lane;
#pragma unroll
    for (int o = 16; o; o >>= 1) {
        float ov = __shfl_xor_sync(0xffffffffu, bv2, o);
        int   oi = __shfl_xor_sync(0xffffffffu, bi2, o);
        if (ov > bv2 || (ov == bv2 && oi < bi2)) { bv2 = ov; bi2 = oi; }
    }
    int i1 = bi2;
    float p0 = __shfl_sync(0xffffffffu, prob, i0);
    float p1 = __shfl_sync(0xffffffffu, prob, i1);
    if (lane == 0) {
        float inv = 1.f / (p0 + p1);
        int s0 = atomicAdd(&g_cnt[i0], 1);
        g_btok[i0 * N_TOK + s0] = n;
        g_bwgt[i0 * N_TOK + s0] = p0 * inv;
        g_pslot[n * 2 + 0] = i0 * N_TOK + s0;
        int s1 = atomicAdd(&g_cnt[i1], 1);
        g_btok[i1 * N_TOK + s1] = n;
        g_bwgt[i1 * N_TOK + s1] = p1 * inv;
        g_pslot[n * 2 + 1] = i1 * N_TOK + s1;
    }
}

// ---------------- K3: down-proj partials via tf32 mma, cvt-at-fill -------------
// grid (16 k-slices, 32 experts, 2 token-tiles), 256 threads.
// Block: 64 tok x 64 l x 64 k. Warp w: tokens [(w&3)*16,+16), l [(w>>2)*32,+32).
__global__ __launch_bounds__(256, 4)
void k3_down(const float* __restrict__ x, const float* __restrict__ w_down) {
    __shared__ unsigned ws[D_LOW * 68];   // [64 l][64 k + pad], tf32 bits
    __shared__ unsigned xs[64 * 68];      // [64 tok][64 k + pad], tf32 bits

    const int e = blockIdx.y;
    const int ks = blockIdx.x;
    const int cnt = g_cnt[e];
    const int tile0 = blockIdx.z * 64;
    if (tile0 >= cnt) return;
    const int tid = threadIdx.x;
    const int off = expert_off(tid & 31, e);

    const float4* wd4 = (const float4*)w_down;
#pragma unroll
    for (int i = 0; i < 4; i++) {
        int j = tid + i * 256;
        int l = j >> 4, cq = j & 15;
        *(uint4*)(ws + l * 68 + cq * 4) =
            f2tf4(wd4[(e * D_LOW + l) * (D_MODEL / 4) + ks * 16 + cq]);
    }

    const int lane = tid & 31, warp = tid >> 5;
    const int mb = (warp & 3) * 16;       // token block
    const int nb = (warp >> 2) * 32;      // l block
    const int grp = lane >> 2, tig = lane & 3;
    const int r0 = tid >> 4, cq0 = tid & 15;
    const float4* x4g = (const float4*)x;

    for (int t0 = tile0; t0 < cnt; t0 += 128) {
#pragma unroll
        for (int j = 0; j < 4; j++) {
            int idx = t0 + r0 + 16 * j; if (idx >= cnt) idx = cnt - 1;
            *(uint4*)(xs + (r0 + 16 * j) * 68 + cq0 * 4) =
                f2tf4(x4g[g_btok[e * N_TOK + idx] * (D_MODEL / 4) + ks * 16 + cq0]);
        }
        __syncthreads();

        float acc[4][4];
#pragma unroll
        for (int nt = 0; nt < 4; nt++)
#pragma unroll
            for (int c = 0; c < 4; c++) acc[nt][c] = 0.f;

#pragma unroll
        for (int k0 = 0; k0 < 64; k0 += 8) {
            unsigned a[4];
            a[0] = xs[(mb + grp    ) * 68 + k0 + tig    ];
            a[1] = xs[(mb + grp + 8) * 68 + k0 + tig    ];
            a[2] = xs[(mb + grp    ) * 68 + k0 + tig + 4];
            a[3] = xs[(mb + grp + 8) * 68 + k0 + tig + 4];
#pragma unroll
            for (int nt = 0; nt < 4; nt++) {
                unsigned b0 = ws[(nb + nt * 8 + grp) * 68 + k0 + tig    ];
                unsigned b1 = ws[(nb + nt * 8 + grp) * 68 + k0 + tig + 4];
                MMA_TF32(acc[nt], a, b0, b1);
            }
        }

        // store D fragments: row = mb+grp(+8), col = nb + nt*8 + 2*tig(+1)
#pragma unroll
        for (int nt = 0; nt < 4; nt++) {
#pragma unroll
            for (int h = 0; h < 2; h++) {
                int s = t0 + mb + grp + 8 * h;
                if (s < cnt) {
                    int col = nb + nt * 8 + 2 * tig;
                    *(float2*)&g_actp[((ks * N_PAIR + off + s) << 6) + col] =
                        make_float2(acc[nt][2 * h], acc[nt][2 * h + 1]);
                }
            }
        }
        __syncthreads();
    }
}

// ---------------- K3g: sum 16 k-slices + GELU -> tf32 (+ aux loss) -------------
__global__ void k3g_gelu(float* out, int write_aux) {
    int tid = threadIdx.x;
    if (blockIdx.x == 0 && tid < 32 && write_aux) {
        float v = g_sumprob[tid] * (float)g_cnt[tid];
#pragma unroll
        for (int o = 16; o; o >>= 1) v += __shfl_xor_sync(0xffffffffu, v, o);
        if (tid == 0)
            out[OUT_ELEMS] = (float)N_EXP * v / ((float)N_TOK * (float)N_TOK);
    }
    int i = blockIdx.x * 256 + tid;               // 128*256 = PS/4
    const float4* ap4 = (const float4*)g_actp;
    float4 s = ap4[i];
#pragma unroll
    for (int k = 1; k < KSPLIT; k++) {
        float4 v = ap4[k * (PS / 4) + i];
        s.x += v.x; s.y += v.y; s.z += v.z; s.w += v.w;
    }
    // store tf32 bit patterns of gelu(s) — k4 consumes these directly
    uint4 o4 = make_uint4(f2tf(gelu_exact(s.x)), f2tf(gelu_exact(s.y)),
                          f2tf(gelu_exact(s.z)), f2tf(gelu_exact(s.w)));
    ((uint4*)g_acts)[i] = o4;
}

// ---------------- K4: up-proj via tf32 mma, cvt-at-fill ------------------------
// grid (16 d-tiles, 32 experts, 2 token-tiles), 256 threads.
// Block: 64 tok x 64 d x 64 l. Warp w: tokens [(w&3)*16), d [(w>>2)*32).
__global__ __launch_bounds__(256, 4)
void k4_up(const float* __restrict__ w_up) {
    __shared__ unsigned wu_s[64 * 68];    // [64 d][64 l + pad], tf32 (transposed)
    __shared__ unsigned as_s[64 * 68];    // [64 tok][64 l + pad], tf32 bits

    const int e = blockIdx.y;
    const int dt = blockIdx.x;
    const int cnt = g_cnt[e];
    const int tile0 = blockIdx.z * 64;
    if (tile0 >= cnt) return;
    const int tid = threadIdx.x;
    const int off = expert_off(tid & 31, e);

    // transpose w_up[e][l][dt*64 + d] -> wu_s[d][l], converting to tf32
#pragma unroll
    for (int i = 0; i < 4; i++) {
        int j = tid + i * 256;
        int d = j & 63, lg = j >> 6;
        const float* base = w_up + (e * D_LOW + lg * 4) * D_MODEL + dt * 64 + d;
        *(uint4*)(wu_s + d * 68 + lg * 4) =
            make_uint4(f2tf(base[0]), f2tf(base[D_MODEL]),
                       f2tf(base[2 * D_MODEL]), f2tf(base[3 * D_MODEL]));
    }

    const int lane = tid & 31, warp = tid >> 5;
    const int mb = (warp & 3) * 16;       // token block
    const int nb = (warp >> 2) * 32;      // d block
    const int grp = lane >> 2, tig = lane & 3;
    const int r0 = tid >> 4, cq0 = tid & 15;
    const uint4* a4g = (const uint4*)g_acts;      // already tf32 bits

    for (int t0 = tile0; t0 < cnt; t0 += 128) {
#pragma unroll
        for (int j = 0; j < 4; j++) {
            int idx = t0 + r0 + 16 * j; if (idx >= cnt) idx = cnt - 1;
            *(uint4*)(as_s + (r0 + 16 * j) * 68 + cq0 * 4) =
                a4g[(off + idx) * (D_LOW / 4) + cq0];
        }
        __syncthreads();

        float acc[4][4];
#pragma unroll
        for (int nt = 0; nt < 4; nt++)
#pragma unroll
            for (int c = 0; c < 4; c++) acc[nt][c] = 0.f;

#pragma unroll
        for (int k0 = 0; k0 < 64; k0 += 8) {
            unsigned a[4];
            a[0] = as_s[(mb + grp    ) * 68 + k0 + tig    ];
            a[1] = as_s[(mb + grp + 8) * 68 + k0 + tig    ];
            a[2] = as_s[(mb + grp    ) * 68 + k0 + tig + 4];
            a[3] = as_s[(mb + grp + 8) * 68 + k0 + tig + 4];
#pragma unroll
            for (int nt = 0; nt < 4; nt++) {
                unsigned b0 = wu_s[(nb + nt * 8 + grp) * 68 + k0 + tig    ];
                unsigned b1 = wu_s[(nb + nt * 8 + grp) * 68 + k0 + tig + 4];
                MMA_TF32(acc[nt], a, b0, b1);
            }
        }

        // store: row token s = t0+mb+grp(+8), col d = dt*64 + nb + nt*8 + 2*tig
#pragma unroll
        for (int h = 0; h < 2; h++) {
            int s = t0 + mb + grp + 8 * h;
            if (s < cnt) {
                float w = g_bwgt[e * N_TOK + s];
                float* yrow = g_y + (off + s) * D_MODEL + dt * 64;
#pragma unroll
                for (int nt = 0; nt < 4; nt++) {
                    int col = nb + nt * 8 + 2 * tig;
                    *(float2*)&yrow[col] =
                        make_float2(w * acc[nt][2 * h], w * acc[nt][2 * h + 1]);
                }
            }
        }
        __syncthreads();
    }
}

// ---------------- K5: gather-combine the two pairs per token ------------------
__global__ void k5_combine(float* __restrict__ out) {
    const int n = blockIdx.x;
    const int tid = threadIdx.x;
    const int lane = tid & 31;
    int cc = g_cnt[lane];
    int sc = cc;
#pragma unroll
    for (int o = 1; o < 32; o <<= 1) {
        int v = __shfl_up_sync(0xffffffffu, sc, o);
        if (lane >= o) sc += v;
    }
    int offl = sc - cc;
    int v0 = g_pslot[n * 2 + 0];
    int v1 = g_pslot[n * 2 + 1];
    int p0 = __shfl_sync(0xffffffffu, offl, v0 >> 10) + (v0 & (N_TOK - 1));
    int p1 = __shfl_sync(0xffffffffu, offl, v1 >> 10) + (v1 & (N_TOK - 1));
    const float4* y4 = (const float4*)g_y;
    float4 a = y4[p0 * (D_MODEL / 4) + tid];
    float4 b = y4[p1 * (D_MODEL / 4) + tid];
    ((float4*)out)[n * (D_MODEL / 4) + tid] =
        make_float4(a.x + b.x, a.y + b.y, a.z + b.z, a.w + b.w);
}

// ---------------- launch ------------------------------------------------------
extern "C" void kernel_launch(void* const* d_in, const int* in_sizes, int n_in,
                              void* d_out, int out_size) {
    const float* x        = (const float*)d_in[0];
    const float* w_down   = (const float*)d_in[1];
    const float* router_w = (const float*)d_in[2];
    const float* w_up     = (const float*)d_in[3];
    float* out = (float*)d_out;

    k1_fold<<<128, 256>>>(w_down, router_w);
    k2a_logits<<<dim3(32, LSPLIT), 256>>>(x);
    k2c_route<<<128, 256>>>();
    k3_down<<<dim3(KSPLIT, N_EXP, 2), 256>>>(x, w_down);
    k3g_gelu<<<128, 256>>>(out, out_size > OUT_ELEMS ? 1 : 0);
    k4_up<<<dim3(16, N_EXP, 2), 256>>>(w_up);
    k5_combine<<<N_TOK, 256>>>(out);
}